// round 14
// baseline (speedup 1.0000x reference)
#include <cuda_runtime.h>

typedef unsigned long long ull;

#define HN 32
#define WARPS 4   // warps per block
#define BPW 4     // batch elements (independent recurrences) per warp, in 2 groups of 2

__device__ __forceinline__ ull pk2(float x, float y) {
    ull r; asm("mov.b64 %0, {%1,%2};" : "=l"(r) : "f"(x), "f"(y)); return r;
}
__device__ __forceinline__ void upk2(ull v, float& x, float& y) {
    asm("mov.b64 {%0,%1}, %2;" : "=f"(x), "=f"(y) : "l"(v));
}
__device__ __forceinline__ ull ffma2(ull a, ull b, ull c) {
    ull d; asm("fma.rn.f32x2 %0, %1, %2, %3;" : "=l"(d) : "l"(a), "l"(b), "l"(c)); return d;
}
__device__ __forceinline__ float ex2f(float x) {
    float r; asm("ex2.approx.f32 %0, %1;" : "=f"(r) : "f"(x)); return r;
}
__device__ __forceinline__ float rcpf(float x) {
    float r; asm("rcp.approx.f32 %0, %1;" : "=f"(r) : "f"(x)); return r;
}
__device__ __forceinline__ float tanha(float x) {
    float r; asm("tanh.approx.f32 %0, %1;" : "=f"(r) : "f"(x)); return r;
}
// accurate versions (used once, in the backward step + head)
__device__ __forceinline__ float sigmoid_f(float a) {
    return rcpf(1.f + ex2f(-1.4426950408889634f * a));
}
__device__ __forceinline__ float tanh_f(float a) {
    float e = ex2f(2.8853900817779268f * a);
    return fmaf(-2.f, rcpf(e + 1.f), 1.f);
}

__global__ __launch_bounds__(WARPS * 32, 1)
void gru_bidir_kernel(const float* __restrict__ x,
                      const float* __restrict__ Wih_f, const float* __restrict__ Whh_f,
                      const float* __restrict__ bih_f, const float* __restrict__ bhh_f,
                      const float* __restrict__ Wih_b, const float* __restrict__ Whh_b,
                      const float* __restrict__ bih_b, const float* __restrict__ bhh_b,
                      const float* __restrict__ W1, const float* __restrict__ b1,
                      const float* __restrict__ W2, const float* __restrict__ b2,
                      float* __restrict__ out, int B, int T)
{
    __shared__ float sx[WARPS][BPW][512];                 // per-batch x rows (T <= 512)
    __shared__ alignas(16) float hd[WARPS][BPW][2][HN];   // double-buffered h per batch
    __shared__ float scat[WARPS][2 * HN];                 // head scratch (reused per batch)

    const int w    = threadIdx.x >> 5;
    const int lane = threadIdx.x & 31;
    const int b0   = (blockIdx.x * WARPS + w) * BPW;      // first batch of this warp
    if (b0 >= B) return;   // no block-level syncs anywhere: safe early exit

    // ---- stage x[b0..b0+3, :] into shared (coalesced float4) ----
#pragma unroll
    for (int bi = 0; bi < BPW; bi++) {
        const float4* xr = reinterpret_cast<const float4*>(x + (size_t)(b0 + bi) * T);
        float4* dst = reinterpret_cast<float4*>(sx[w][bi]);
        for (int i = lane; i < (T >> 2); i += 32) dst[i] = xr[i];
    }

    // ---- recurrent weights, pairwise-over-j packed; r/z rows prescaled by 0.5
    //      (sigmoid(a) = 0.5*tanh(0.5*a)+0.5, fold the 0.5 into the affine form)
    ull wr[16], wz[16], wn[16];
#pragma unroll
    for (int k = 0; k < 16; k++) {
        wr[k] = pk2(0.5f * __ldg(&Whh_f[lane * HN + 2 * k]),
                    0.5f * __ldg(&Whh_f[lane * HN + 2 * k + 1]));
        wz[k] = pk2(0.5f * __ldg(&Whh_f[(lane + 32) * HN + 2 * k]),
                    0.5f * __ldg(&Whh_f[(lane + 32) * HN + 2 * k + 1]));
        wn[k] = pk2(__ldg(&Whh_f[(lane + 64) * HN + 2 * k]),
                    __ldg(&Whh_f[(lane + 64) * HN + 2 * k + 1]));
    }
    const ull  ir = pk2(0.5f * (bih_f[lane]      + bhh_f[lane]),      0.f);
    const ull  iz = pk2(0.5f * (bih_f[lane + 32] + bhh_f[lane + 32]), 0.f);
    const ull  in = pk2(bhh_f[lane + 64],                             0.f);
    const float wih_r = 0.5f * Wih_f[lane];
    const float wih_z = 0.5f * Wih_f[lane + 32];
    const float wih_n = Wih_f[lane + 64];
    const float bih_n = bih_f[lane + 64];

    // ---- per-batch state ----
    ull ar[BPW], az[BPW], an_[BPW];
    float xv[BPW], hself[BPW];

    // matvec for batch pair {g, g+1}: read h from hd[..][buf], x from step tt
    auto matvec_pair = [&](int g, int buf, int tt) {
#pragma unroll
        for (int u = 0; u < 2; u++) {
            const int bi = g + u;
            ar[bi] = ir; az[bi] = iz; an_[bi] = in;
            xv[bi] = sx[w][bi][tt];
        }
#pragma unroll
        for (int q = 0; q < 8; q++) {
#pragma unroll
            for (int u = 0; u < 2; u++) {
                const int bi = g + u;
                ulonglong2 hp = reinterpret_cast<const ulonglong2*>(hd[w][bi][buf])[q];
                ar[bi]  = ffma2(wr[2 * q],     hp.x, ar[bi]);
                az[bi]  = ffma2(wz[2 * q],     hp.x, az[bi]);
                an_[bi] = ffma2(wn[2 * q],     hp.x, an_[bi]);
                ar[bi]  = ffma2(wr[2 * q + 1], hp.y, ar[bi]);
                az[bi]  = ffma2(wz[2 * q + 1], hp.y, az[bi]);
                an_[bi] = ffma2(wn[2 * q + 1], hp.y, an_[bi]);
            }
        }
    };

    // activation for batch pair {g, g+1}: consume acc + xv, store h_new into hd[..][buf]
    auto act_pair = [&](int g, int buf) {
#pragma unroll
        for (int u = 0; u < 2; u++) {
            const int bi = g + u;
            float rlo, rhi, zlo, zhi, nlo, nhi;
            upk2(ar[bi], rlo, rhi); upk2(az[bi], zlo, zhi); upk2(an_[bi], nlo, nhi);
            const float r = fmaf(tanha(fmaf(xv[bi], wih_r, rlo + rhi)), 0.5f, 0.5f);
            const float z = fmaf(tanha(fmaf(xv[bi], wih_z, zlo + zhi)), 0.5f, 0.5f);
            const float an = fmaf(r, nlo + nhi, fmaf(xv[bi], wih_n, bih_n));
            const float n  = tanha(an);
            hself[bi] = fmaf(z, hself[bi] - n, n);
            hd[w][bi][buf][lane] = hself[bi];
        }
    };

    // ---- prologue: h=0 in buffer 0; A's matvec(0) from h=0 is just the biases ----
#pragma unroll
    for (int bi = 0; bi < BPW; bi++) {
        hself[bi] = 0.f;
        hd[w][bi][0][lane] = 0.f;
    }
    ar[0] = ar[1] = ir; az[0] = az[1] = iz; an_[0] = an_[1] = in;
    __syncwarp();                 // covers x staging + h init
    xv[0] = sx[w][0][0];
    xv[1] = sx[w][1][0];

    // ---- forward scan: 2-stage pipeline, group A skewed half a step ahead ----
    // invariant at loop entry: acc[A] = matvec(A, t), xv[A] = x[t]; hd holds hB[t] in buf (t&1)
#pragma unroll 1
    for (int t = 0; t < T; t++) {
        const int cur = t & 1, nxt = cur ^ 1;

        act_pair(0, nxt);                         // A: h[t+1], overlaps with...
        matvec_pair(2, cur, t);                   // B: matvec(t) from hB[t]
        __syncwarp();

        act_pair(2, nxt);                         // B: h[t+1], overlaps with...
        matvec_pair(0, nxt, (t + 1 < T) ? t + 1 : t);   // A: matvec(t+1) from hA[t+1]
        __syncwarp();
    }

    // ---- backward direction (ONE step from h0=0 on x[T-1]) + MLP head ----
    // accurate activations here: paid once, keeps the head contribution tight
#pragma unroll
    for (int bi = 0; bi < BPW; bi++) {
        const float xl = sx[w][bi][T - 1];
        const float arb = fmaf(xl, Wih_b[lane],      bih_b[lane])      + bhh_b[lane];
        const float azb = fmaf(xl, Wih_b[lane + 32], bih_b[lane + 32]) + bhh_b[lane + 32];
        const float anx = fmaf(xl, Wih_b[lane + 64], bih_b[lane + 64]);
        const float r = sigmoid_f(arb);
        const float z = sigmoid_f(azb);
        const float n = tanh_f(fmaf(r, bhh_b[lane + 64], anx));
        const float hb = (1.f - z) * n;

        scat[w][lane]      = hself[bi];   // forward final hidden
        scat[w][HN + lane] = hb;          // backward "last" hidden
        __syncwarp();

        float v = 0.f;
        if (lane < 16) {
            float a = b1[lane];
            const float* w1r = W1 + lane * 64;
#pragma unroll
            for (int k = 0; k < 64; k++) a = fmaf(scat[w][k], __ldg(&w1r[k]), a);
            a = fmaxf(a, 0.f);
            v = a * W2[lane];
        }
#pragma unroll
        for (int off = 16; off; off >>= 1) v += __shfl_xor_sync(0xffffffffu, v, off);
        if (lane == 0 && b0 + bi < B) out[b0 + bi] = sigmoid_f(v + b2[0]);
        __syncwarp();
    }
}

extern "C" void kernel_launch(void* const* d_in, const int* in_sizes, int n_in,
                              void* d_out, int out_size)
{
    const float* x     = (const float*)d_in[0];
    const float* Wih_f = (const float*)d_in[1];
    const float* Whh_f = (const float*)d_in[2];
    const float* bih_f = (const float*)d_in[3];
    const float* bhh_f = (const float*)d_in[4];
    const float* Wih_b = (const float*)d_in[5];
    const float* Whh_b = (const float*)d_in[6];
    const float* bih_b = (const float*)d_in[7];
    const float* bhh_b = (const float*)d_in[8];
    const float* W1    = (const float*)d_in[9];
    const float* b1    = (const float*)d_in[10];
    const float* W2    = (const float*)d_in[11];
    const float* b2    = (const float*)d_in[12];

    const int B = out_size;                 // output is [B, 1] float32
    const int T = in_sizes[0] / B;          // x is [B, T, 1]

    const int batches_per_block = WARPS * BPW;
    const int blocks = (B + batches_per_block - 1) / batches_per_block;
    gru_bidir_kernel<<<blocks, WARPS * 32>>>(x, Wih_f, Whh_f, bih_f, bhh_f,
                                             Wih_b, Whh_b, bih_b, bhh_b,
                                             W1, b1, W2, b2,
                                             (float*)d_out, B, T);
}

// round 17
// speedup vs baseline: 1.0804x; 1.0804x over previous
#include <cuda_runtime.h>

typedef unsigned long long ull;

#define HN 32
#define WARPS 4   // warps per block
#define BPW 4     // batch elements (independent recurrences) per warp

__device__ __forceinline__ ull pk2(float x, float y) {
    ull r; asm("mov.b64 %0, {%1,%2};" : "=l"(r) : "f"(x), "f"(y)); return r;
}
__device__ __forceinline__ void upk2(ull v, float& x, float& y) {
    asm("mov.b64 {%0,%1}, %2;" : "=f"(x), "=f"(y) : "l"(v));
}
__device__ __forceinline__ ull ffma2(ull a, ull b, ull c) {
    ull d; asm("fma.rn.f32x2 %0, %1, %2, %3;" : "=l"(d) : "l"(a), "l"(b), "l"(c)); return d;
}
__device__ __forceinline__ float ex2f(float x) {
    float r; asm("ex2.approx.f32 %0, %1;" : "=f"(r) : "f"(x)); return r;
}
__device__ __forceinline__ float rcpf(float x) {
    float r; asm("rcp.approx.f32 %0, %1;" : "=f"(r) : "f"(x)); return r;
}
__device__ __forceinline__ float tanha(float x) {
    float r; asm("tanh.approx.f32 %0, %1;" : "=f"(r) : "f"(x)); return r;
}
// accurate versions (used once, in the backward step + head)
__device__ __forceinline__ float sigmoid_f(float a) {
    return rcpf(1.f + ex2f(-1.4426950408889634f * a));
}
__device__ __forceinline__ float tanh_f(float a) {
    float e = ex2f(2.8853900817779268f * a);
    return fmaf(-2.f, rcpf(e + 1.f), 1.f);
}

__global__ __launch_bounds__(WARPS * 32, 1)
void gru_bidir_kernel(const float* __restrict__ x,
                      const float* __restrict__ Wih_f, const float* __restrict__ Whh_f,
                      const float* __restrict__ bih_f, const float* __restrict__ bhh_f,
                      const float* __restrict__ Wih_b, const float* __restrict__ Whh_b,
                      const float* __restrict__ bih_b, const float* __restrict__ bhh_b,
                      const float* __restrict__ W1, const float* __restrict__ b1,
                      const float* __restrict__ W2, const float* __restrict__ b2,
                      float* __restrict__ out, int B, int T)
{
    __shared__ alignas(16) float sxT[WARPS][512][BPW];    // transposed x: [t][batch]
    __shared__ alignas(16) float hd[WARPS][BPW][2][HN];   // double-buffered h per batch
    __shared__ float scat[WARPS][2 * HN];                 // head scratch (reused per batch)

    const int w    = threadIdx.x >> 5;
    const int lane = threadIdx.x & 31;
    const int b0   = (blockIdx.x * WARPS + w) * BPW;      // first batch of this warp
    if (b0 >= B) return;   // no block-level syncs anywhere: safe early exit

    // ---- stage x[b0..b0+3, :] into shared, TRANSPOSED so one LDS.128 serves
    //      all 4 batches at a given t (one-time cost; conflicts acceptable) ----
#pragma unroll
    for (int bi = 0; bi < BPW; bi++) {
        const float4* xr = reinterpret_cast<const float4*>(x + (size_t)(b0 + bi) * T);
        for (int i = lane; i < (T >> 2); i += 32) {
            float4 v = xr[i];
            sxT[w][i * 4 + 0][bi] = v.x;
            sxT[w][i * 4 + 1][bi] = v.y;
            sxT[w][i * 4 + 2][bi] = v.z;
            sxT[w][i * 4 + 3][bi] = v.w;
        }
    }

    // ---- recurrent weights, pairwise-over-j packed; r/z rows prescaled by 0.5
    //      (sigmoid(a) = 0.5*tanh(0.5*a)+0.5, fold the 0.5 into the affine form)
    ull wr[16], wz[16], wn[16];
#pragma unroll
    for (int k = 0; k < 16; k++) {
        wr[k] = pk2(0.5f * __ldg(&Whh_f[lane * HN + 2 * k]),
                    0.5f * __ldg(&Whh_f[lane * HN + 2 * k + 1]));
        wz[k] = pk2(0.5f * __ldg(&Whh_f[(lane + 32) * HN + 2 * k]),
                    0.5f * __ldg(&Whh_f[(lane + 32) * HN + 2 * k + 1]));
        wn[k] = pk2(__ldg(&Whh_f[(lane + 64) * HN + 2 * k]),
                    __ldg(&Whh_f[(lane + 64) * HN + 2 * k + 1]));
    }
    const float ir_lo = 0.5f * (bih_f[lane]      + bhh_f[lane]);
    const float iz_lo = 0.5f * (bih_f[lane + 32] + bhh_f[lane + 32]);
    const ull   in    = pk2(bhh_f[lane + 64], 0.f);
    const float wih_r = 0.5f * Wih_f[lane];
    const float wih_z = 0.5f * Wih_f[lane + 32];
    const float wih_n = Wih_f[lane + 64];
    const float bih_n = bih_f[lane + 64];

    // ---- init h = 0 for all batches ----
    float hself[BPW];
#pragma unroll
    for (int bi = 0; bi < BPW; bi++) {
        hself[bi] = 0.f;
        hd[w][bi][0][lane] = 0.f;
    }
    __syncwarp();

    // one GRU step for all 4 batches; cur/nxt are compile-time
    auto step = [&](int t, int cur, int nxt) {
        // all 4 batches' x[t] in one broadcast LDS.128
        const float4 xq = *reinterpret_cast<const float4*>(&sxT[w][t][0]);
        const float xv[BPW] = {xq.x, xq.y, xq.z, xq.w};

        ull ar[BPW], az[BPW], an_[BPW];
        float xn[BPW];
#pragma unroll
        for (int bi = 0; bi < BPW; bi++) {
            // fold x-input terms into the init (off the post-matvec tail)
            ar[bi] = pk2(fmaf(xv[bi], wih_r, ir_lo), 0.f);
            az[bi] = pk2(fmaf(xv[bi], wih_z, iz_lo), 0.f);
            an_[bi] = in;
            xn[bi] = fmaf(xv[bi], wih_n, bih_n);
        }

#pragma unroll
        for (int q = 0; q < 8; q++) {
#pragma unroll
            for (int bi = 0; bi < BPW; bi++) {
                ulonglong2 hp = reinterpret_cast<const ulonglong2*>(hd[w][bi][cur])[q];
                ar[bi]  = ffma2(wr[2 * q],     hp.x, ar[bi]);
                az[bi]  = ffma2(wz[2 * q],     hp.x, az[bi]);
                an_[bi] = ffma2(wn[2 * q],     hp.x, an_[bi]);
                ar[bi]  = ffma2(wr[2 * q + 1], hp.y, ar[bi]);
                az[bi]  = ffma2(wz[2 * q + 1], hp.y, az[bi]);
                an_[bi] = ffma2(wn[2 * q + 1], hp.y, an_[bi]);
            }
        }

#pragma unroll
        for (int bi = 0; bi < BPW; bi++) {
            float rlo, rhi, zlo, zhi, nlo, nhi;
            upk2(ar[bi], rlo, rhi); upk2(az[bi], zlo, zhi); upk2(an_[bi], nlo, nhi);
            const float r = fmaf(tanha(rlo + rhi), 0.5f, 0.5f);
            const float z = fmaf(tanha(zlo + zhi), 0.5f, 0.5f);
            const float n = tanha(fmaf(r, nlo + nhi, xn[bi]));
            hself[bi] = fmaf(z, hself[bi] - n, n);
            hd[w][bi][nxt][lane] = hself[bi];
        }
        __syncwarp();
    };

    // ---- forward scan, unrolled x2 with fixed buffer roles ----
    int t = 0;
    for (; t + 1 < T; t += 2) {
        step(t,     0, 1);
        step(t + 1, 1, 0);
    }
    if (t < T) step(t, 0, 1);   // odd-T safety (T=512 in practice)

    // ---- backward direction (ONE step from h0=0 on x[T-1]) + MLP head ----
    // accurate activations here: paid once, keeps the head contribution tight
#pragma unroll
    for (int bi = 0; bi < BPW; bi++) {
        const float xl = sxT[w][T - 1][bi];
        const float arb = fmaf(xl, Wih_b[lane],      bih_b[lane])      + bhh_b[lane];
        const float azb = fmaf(xl, Wih_b[lane + 32], bih_b[lane + 32]) + bhh_b[lane + 32];
        const float anx = fmaf(xl, Wih_b[lane + 64], bih_b[lane + 64]);
        const float r = sigmoid_f(arb);
        const float z = sigmoid_f(azb);
        const float n = tanh_f(fmaf(r, bhh_b[lane + 64], anx));
        const float hb = (1.f - z) * n;

        scat[w][lane]      = hself[bi];   // forward final hidden
        scat[w][HN + lane] = hb;          // backward "last" hidden
        __syncwarp();

        float v = 0.f;
        if (lane < 16) {
            float a = b1[lane];
            const float* w1r = W1 + lane * 64;
#pragma unroll
            for (int k = 0; k < 64; k++) a = fmaf(scat[w][k], __ldg(&w1r[k]), a);
            a = fmaxf(a, 0.f);
            v = a * W2[lane];
        }
#pragma unroll
        for (int off = 16; off; off >>= 1) v += __shfl_xor_sync(0xffffffffu, v, off);
        if (lane == 0 && b0 + bi < B) out[b0 + bi] = sigmoid_f(v + b2[0]);
        __syncwarp();
    }
}

extern "C" void kernel_launch(void* const* d_in, const int* in_sizes, int n_in,
                              void* d_out, int out_size)
{
    const float* x     = (const float*)d_in[0];
    const float* Wih_f = (const float*)d_in[1];
    const float* Whh_f = (const float*)d_in[2];
    const float* bih_f = (const float*)d_in[3];
    const float* bhh_f = (const float*)d_in[4];
    const float* Wih_b = (const float*)d_in[5];
    const float* Whh_b = (const float*)d_in[6];
    const float* bih_b = (const float*)d_in[7];
    const float* bhh_b = (const float*)d_in[8];
    const float* W1    = (const float*)d_in[9];
    const float* b1    = (const float*)d_in[10];
    const float* W2    = (const float*)d_in[11];
    const float* b2    = (const float*)d_in[12];

    const int B = out_size;                 // output is [B, 1] float32
    const int T = in_sizes[0] / B;          // x is [B, T, 1]

    const int batches_per_block = WARPS * BPW;
    const int blocks = (B + batches_per_block - 1) / batches_per_block;
    gru_bidir_kernel<<<blocks, WARPS * 32>>>(x, Wih_f, Whh_f, bih_f, bhh_f,
                                             Wih_b, Whh_b, bih_b, bhh_b,
                                             W1, b1, W2, b2,
                                             (float*)d_out, B, T);
}